// round 8
// baseline (speedup 1.0000x reference)
#include <cuda_runtime.h>
#include <cuda_bf16.h>
#include <mma.h>
#include <cstdint>

using namespace nvcuda;

#define T_STEPS 512
#define BATCH   64
#define DIN     1024
#define HID     1024
#define N3      3072   // [z | r | c] precomputed x-projections
#define MROWS   (T_STEPS * BATCH)   // 32768

// ---------------- static device scratch (no runtime allocation) ----------------
__device__ float g_P[(size_t)MROWS * N3];               // 384 MB: x-projections (fp32)
__device__ __nv_bfloat16 g_Xh[(size_t)MROWS * DIN];     // X hi (bf16)
__device__ __nv_bfloat16 g_Xl[(size_t)MROWS * DIN];     // X lo
__device__ __nv_bfloat16 g_Bh[(size_t)N3 * DIN];        // phase-1 W rows [n][k] hi
__device__ __nv_bfloat16 g_Bl[(size_t)N3 * DIN];        // phase-1 W rows [n][k] lo
__device__ __nv_bfloat16 g_WAh[2048 * 1024];            // Wfc h-part rows [n][k] hi
__device__ __nv_bfloat16 g_WAl[2048 * 1024];            // lo
__device__ __nv_bfloat16 g_WBh[1024 * 1024];            // Wfc2 h-part rows [n][k] hi
__device__ __nv_bfloat16 g_WBl[1024 * 1024];            // lo
__device__ float g_hb[BATCH * HID];                     // h fp32 (carried state)
__device__ __nv_bfloat16 g_hbh[BATCH * HID];            // h hi
__device__ __nv_bfloat16 g_hbl[BATCH * HID];            // h lo
__device__ float g_PA[8 * BATCH * 2048];                // split-K partials stage A (4MB)
__device__ float g_PB[16 * BATCH * HID];                // split-K partials stage B (4MB)
__device__ volatile unsigned g_bar;                     // grid barrier counter

// ---------------- init ----------------
__global__ void init_kernel() {
    int i = blockIdx.x * blockDim.x + threadIdx.x;
    if (i == 0) g_bar = 0u;
    if (i < HID * BATCH) {
        float h0 = 1e-9f;
        g_hb[i] = h0;
        __nv_bfloat16 hh = __float2bfloat16(h0);
        g_hbh[i] = hh;
        g_hbl[i] = __float2bfloat16(h0 - __bfloat162float(hh));
    }
}

// ---------------- convert: fp32 -> bf16 hi/lo for X and all weight views ----------------
__global__ void convert_kernel(const float* __restrict__ x,
                               const float* __restrict__ Wfc,
                               const float* __restrict__ Wfc2) {
    int i = blockIdx.x * blockDim.x + threadIdx.x;
    const size_t NX = (size_t)MROWS * DIN;
    if ((size_t)i < NX) {
        float a = x[i];
        __nv_bfloat16 h = __float2bfloat16(a);
        g_Xh[i] = h;
        g_Xl[i] = __float2bfloat16(a - __bfloat162float(h));
    }
    if (i < N3 * DIN) {            // phase-1 weights: x-part rows
        int n = i >> 10, k = i & 1023;
        float a = (n < 2048) ? Wfc[(size_t)n * 2048 + k]
                             : Wfc2[(size_t)(n - 2048) * 2048 + k];
        __nv_bfloat16 h = __float2bfloat16(a);
        g_Bh[i] = h;
        g_Bl[i] = __float2bfloat16(a - __bfloat162float(h));
    }
    if (i < 2048 * 1024) {         // Wfc h-part rows
        int n = i >> 10, k = i & 1023;
        float a = Wfc[(size_t)n * 2048 + 1024 + k];
        __nv_bfloat16 h = __float2bfloat16(a);
        g_WAh[i] = h;
        g_WAl[i] = __float2bfloat16(a - __bfloat162float(h));
    }
    if (i < 1024 * 1024) {         // Wfc2 h-part rows
        int n = i >> 10, k = i & 1023;
        float a = Wfc2[(size_t)n * 2048 + 1024 + k];
        __nv_bfloat16 h = __float2bfloat16(a);
        g_WBh[i] = h;
        g_WBl[i] = __float2bfloat16(a - __bfloat162float(h));
    }
}

// ---------------- phase 1 (WMMA bf16 hi/lo split): P = X @ W^T ----------------
#define LDT 40

__global__ void __launch_bounds__(256) gemm_p_wmma_kernel() {
    __shared__ __nv_bfloat16 Ah[128][LDT];
    __shared__ __nv_bfloat16 Al[128][LDT];
    __shared__ __nv_bfloat16 Bh[128][LDT];
    __shared__ __nv_bfloat16 Bl[128][LDT];

    const int tid = threadIdx.x, wid = tid >> 5;
    const int m0 = (blockIdx.x / 24) << 7;
    const int n0 = (blockIdx.x % 24) << 7;
    const int wm = (wid >> 2) << 6;
    const int wn = (wid & 3) << 5;

    wmma::fragment<wmma::accumulator, 16, 16, 16, float> acc[4][2];
#pragma unroll
    for (int i = 0; i < 4; i++)
#pragma unroll
        for (int j = 0; j < 2; j++) wmma::fill_fragment(acc[i][j], 0.0f);

    for (int k0 = 0; k0 < DIN; k0 += 32) {
#pragma unroll
        for (int i = tid; i < 512; i += 256) {
            int r = i >> 2, c = (i & 3) << 3;
            *(float4*)&Ah[r][c] = *(const float4*)(g_Xh + (size_t)(m0 + r) * DIN + k0 + c);
            *(float4*)&Al[r][c] = *(const float4*)(g_Xl + (size_t)(m0 + r) * DIN + k0 + c);
            *(float4*)&Bh[r][c] = *(const float4*)(g_Bh + (size_t)(n0 + r) * DIN + k0 + c);
            *(float4*)&Bl[r][c] = *(const float4*)(g_Bl + (size_t)(n0 + r) * DIN + k0 + c);
        }
        __syncthreads();
#pragma unroll
        for (int kk = 0; kk < 32; kk += 16) {
            wmma::fragment<wmma::matrix_a, 16, 16, 16, __nv_bfloat16, wmma::row_major> fah[4], fal[4];
            wmma::fragment<wmma::matrix_b, 16, 16, 16, __nv_bfloat16, wmma::col_major> fbh[2], fbl[2];
#pragma unroll
            for (int i = 0; i < 4; i++) {
                wmma::load_matrix_sync(fah[i], &Ah[wm + i * 16][kk], LDT);
                wmma::load_matrix_sync(fal[i], &Al[wm + i * 16][kk], LDT);
            }
#pragma unroll
            for (int j = 0; j < 2; j++) {
                wmma::load_matrix_sync(fbh[j], &Bh[wn + j * 16][kk], LDT);
                wmma::load_matrix_sync(fbl[j], &Bl[wn + j * 16][kk], LDT);
            }
#pragma unroll
            for (int i = 0; i < 4; i++)
#pragma unroll
                for (int j = 0; j < 2; j++) {
                    wmma::mma_sync(acc[i][j], fah[i], fbh[j], acc[i][j]);
                    wmma::mma_sync(acc[i][j], fah[i], fbl[j], acc[i][j]);
                    wmma::mma_sync(acc[i][j], fal[i], fbh[j], acc[i][j]);
                }
        }
        __syncthreads();
    }
#pragma unroll
    for (int i = 0; i < 4; i++)
#pragma unroll
        for (int j = 0; j < 2; j++)
            wmma::store_matrix_sync(
                g_P + (size_t)(m0 + wm + i * 16) * N3 + n0 + wn + j * 16,
                acc[i][j], N3, wmma::mem_row_major);
}

// ---------------- robust grid barrier (monotonic counter) ----------------
__device__ __forceinline__ void grid_bar(unsigned target) {
    __threadfence();
    __syncthreads();
    if (threadIdx.x == 0) {
        atomicAdd((unsigned*)&g_bar, 1u);
        while (g_bar < target) __nanosleep(64);
        __threadfence();
    }
    __syncthreads();
}

// ---------------- persistent sequential kernel (WMMA, 30KB STATIC smem) ----------------
// Tiles (reused by stage A and stage B): A 64x32 hi/lo + B 128x32 hi/lo, pitch 40.
__global__ void __launch_bounds__(256, 1) seq_kernel(float* __restrict__ out) {
    __shared__ __nv_bfloat16 sAh[64][40];
    __shared__ __nv_bfloat16 sAl[64][40];
    __shared__ __nv_bfloat16 sBh[128][40];
    __shared__ __nv_bfloat16 sBl[128][40];

    const int tid = threadIdx.x, bid = blockIdx.x, nb = gridDim.x;
    const int wid = tid >> 5;
    const int gtid = bid * 256 + tid, nthr = nb * 256;
    const int wm = (wid >> 2) << 5;   // warp row: 0 or 32
    const int wn = (wid & 3) << 5;    // warp col: 0,32,64,96
    unsigned bar_t = 0;

    for (int t = 0; t < T_STEPS; t++) {
        const float* Pt = g_P + (size_t)t * (BATCH * N3);

        // ======== stage A: PA[kc] = h @ WA^T slices  (8 kc x 16 ct = 128 units, 64x128 @K=128)
        for (int u = bid; u < 128; u += nb) {
            const int kc = u >> 4, ct = u & 15;
            const int k0 = kc << 7, n0 = ct << 7;

            wmma::fragment<wmma::accumulator, 16, 16, 16, float> acc[2][2];
#pragma unroll
            for (int i = 0; i < 2; i++)
#pragma unroll
                for (int j = 0; j < 2; j++) wmma::fill_fragment(acc[i][j], 0.0f);

            for (int cc = 0; cc < 128; cc += 32) {
                // A: h[64][k0+cc .. +32] hi/lo (mutable -> ldcg). 256 uint4 per tile.
                {
                    int r = tid >> 2, c = (tid & 3) << 3;
                    *(uint4*)&sAh[r][c] =
                        __ldcg((const uint4*)(g_hbh + (size_t)r * HID + k0 + cc + c));
                    *(uint4*)&sAl[r][c] =
                        __ldcg((const uint4*)(g_hbl + (size_t)r * HID + k0 + cc + c));
                }
                // B: WA rows [n0..n0+128][k0+cc .. +32] hi/lo. 512 uint4 per tile.
#pragma unroll
                for (int i = tid; i < 512; i += 256) {
                    int r = i >> 2, c = (i & 3) << 3;
                    *(uint4*)&sBh[r][c] =
                        *(const uint4*)(g_WAh + (size_t)(n0 + r) * 1024 + k0 + cc + c);
                    *(uint4*)&sBl[r][c] =
                        *(const uint4*)(g_WAl + (size_t)(n0 + r) * 1024 + k0 + cc + c);
                }
                __syncthreads();
#pragma unroll
                for (int kk = 0; kk < 32; kk += 16) {
                    wmma::fragment<wmma::matrix_a, 16, 16, 16, __nv_bfloat16, wmma::row_major> fah[2], fal[2];
                    wmma::fragment<wmma::matrix_b, 16, 16, 16, __nv_bfloat16, wmma::col_major> fbh[2], fbl[2];
#pragma unroll
                    for (int i = 0; i < 2; i++) {
                        wmma::load_matrix_sync(fah[i], &sAh[wm + i * 16][kk], 40);
                        wmma::load_matrix_sync(fal[i], &sAl[wm + i * 16][kk], 40);
                    }
#pragma unroll
                    for (int j = 0; j < 2; j++) {
                        wmma::load_matrix_sync(fbh[j], &sBh[wn + j * 16][kk], 40);
                        wmma::load_matrix_sync(fbl[j], &sBl[wn + j * 16][kk], 40);
                    }
#pragma unroll
                    for (int i = 0; i < 2; i++)
#pragma unroll
                        for (int j = 0; j < 2; j++) {
                            wmma::mma_sync(acc[i][j], fah[i], fbh[j], acc[i][j]);
                            wmma::mma_sync(acc[i][j], fah[i], fbl[j], acc[i][j]);
                            wmma::mma_sync(acc[i][j], fal[i], fbh[j], acc[i][j]);
                        }
                }
                __syncthreads();
            }
#pragma unroll
            for (int i = 0; i < 2; i++)
#pragma unroll
                for (int j = 0; j < 2; j++)
                    wmma::store_matrix_sync(
                        g_PA + (size_t)kc * (BATCH * 2048) + (size_t)(wm + i * 16) * 2048 + n0 + wn + j * 16,
                        acc[i][j], 2048, wmma::mem_row_major);
        }
        bar_t += nb; grid_bar(bar_t);

        // ======== stage B: fused r-reduce + (r*h) @ WB^T  (16 kc x 8 ct = 128 units, 64x128 @K=64)
        for (int u = bid; u < 128; u += nb) {
            const int kc = u >> 3, ct = u & 7;
            const int ks0 = kc << 6, n0 = ct << 7;

            wmma::fragment<wmma::accumulator, 16, 16, 16, float> acc[2][2];
#pragma unroll
            for (int i = 0; i < 2; i++)
#pragma unroll
                for (int j = 0; j < 2; j++) wmma::fill_fragment(acc[i][j], 0.0f);

            for (int cc = 0; cc < 64; cc += 32) {
                // prologue: rh = sigmoid(r-sum)*h for k in [ks0+cc, +32), 64 batches
#pragma unroll
                for (int idx = tid; idx < 2048; idx += 256) {
                    int kl = idx & 31, b = idx >> 5;
                    int k = ks0 + cc + kl;
                    float s = Pt[b * N3 + 1024 + k];
#pragma unroll
                    for (int c = 0; c < 8; c++)
                        s += __ldcg(&g_PA[c * (BATCH * 2048) + b * 2048 + 1024 + k]);
                    float r = 1.0f / (1.0f + __expf(-s));
                    float rh = r * __ldcg(&g_hb[(b << 10) + k]);
                    __nv_bfloat16 hi = __float2bfloat16(rh);
                    sAh[b][kl] = hi;
                    sAl[b][kl] = __float2bfloat16(rh - __bfloat162float(hi));
                }
                // B: WB rows [n0..n0+128][ks0+cc .. +32] hi/lo
#pragma unroll
                for (int i = tid; i < 512; i += 256) {
                    int r = i >> 2, c = (i & 3) << 3;
                    *(uint4*)&sBh[r][c] =
                        *(const uint4*)(g_WBh + (size_t)(n0 + r) * 1024 + ks0 + cc + c);
                    *(uint4*)&sBl[r][c] =
                        *(const uint4*)(g_WBl + (size_t)(n0 + r) * 1024 + ks0 + cc + c);
                }
                __syncthreads();
#pragma unroll
                for (int kk = 0; kk < 32; kk += 16) {
                    wmma::fragment<wmma::matrix_a, 16, 16, 16, __nv_bfloat16, wmma::row_major> fah[2], fal[2];
                    wmma::fragment<wmma::matrix_b, 16, 16, 16, __nv_bfloat16, wmma::col_major> fbh[2], fbl[2];
#pragma unroll
                    for (int i = 0; i < 2; i++) {
                        wmma::load_matrix_sync(fah[i], &sAh[wm + i * 16][kk], 40);
                        wmma::load_matrix_sync(fal[i], &sAl[wm + i * 16][kk], 40);
                    }
#pragma unroll
                    for (int j = 0; j < 2; j++) {
                        wmma::load_matrix_sync(fbh[j], &sBh[wn + j * 16][kk], 40);
                        wmma::load_matrix_sync(fbl[j], &sBl[wn + j * 16][kk], 40);
                    }
#pragma unroll
                    for (int i = 0; i < 2; i++)
#pragma unroll
                        for (int j = 0; j < 2; j++) {
                            wmma::mma_sync(acc[i][j], fah[i], fbh[j], acc[i][j]);
                            wmma::mma_sync(acc[i][j], fah[i], fbl[j], acc[i][j]);
                            wmma::mma_sync(acc[i][j], fal[i], fbh[j], acc[i][j]);
                        }
                }
                __syncthreads();
            }
#pragma unroll
            for (int i = 0; i < 2; i++)
#pragma unroll
                for (int j = 0; j < 2; j++)
                    wmma::store_matrix_sync(
                        g_PB + (size_t)kc * (BATCH * 1024) + (size_t)(wm + i * 16) * 1024 + n0 + wn + j * 16,
                        acc[i][j], 1024, wmma::mem_row_major);
        }
        bar_t += nb; grid_bar(bar_t);

        // ======== stage C: z reduce + tanh(c) + blend + h update (+ bf16 mirror) + output
        float* ot = out + (size_t)t * (BATCH * HID);
        for (int o = gtid; o < BATCH * HID; o += nthr) {
            int b = o >> 10, j = o & 1023;
            float sz = Pt[b * N3 + j];
#pragma unroll
            for (int c = 0; c < 8; c++)
                sz += __ldcg(&g_PA[c * (BATCH * 2048) + b * 2048 + j]);
            float z = 1.0f / (1.0f + __expf(-sz));

            float sc = Pt[b * N3 + 2048 + j];
#pragma unroll
            for (int c = 0; c < 16; c++)
                sc += __ldcg(&g_PB[c * (BATCH * 1024) + o]);
            float cv = tanhf(sc);

            float hcur = __ldcg(&g_hb[o]);
            float hn = fmaf(z, cv - hcur, hcur);   // (1-z)*h + z*c
            ot[o] = hn;
            g_hb[o] = hn;
            __nv_bfloat16 hh = __float2bfloat16(hn);
            g_hbh[o] = hh;
            g_hbl[o] = __float2bfloat16(hn - __bfloat162float(hh));
        }
        bar_t += nb; grid_bar(bar_t);
    }
}

// ---------------- launch (4 graph nodes total) ----------------
extern "C" void kernel_launch(void* const* d_in, const int* in_sizes, int n_in,
                              void* d_out, int out_size) {
    const float* x    = (const float*)d_in[0];   // [512, 64, 1024]
    const float* Wfc  = (const float*)d_in[1];   // [2048, 2048]
    const float* Wfc2 = (const float*)d_in[2];   // [1024, 2048]
    // d_in[3] (w_hh), d_in[4] (bias): dead — delta_u never reaches the output
    float* out = (float*)d_out;                  // [512, 64, 1024]

    int sms = 148;
    cudaDeviceGetAttribute(&sms, cudaDevAttrMultiProcessorCount, 0);
    if (sms > 148) sms = 148;

    init_kernel<<<256, 256>>>();
    convert_kernel<<<(MROWS * DIN + 255) / 256, 256>>>(x, Wfc, Wfc2);
    gemm_p_wmma_kernel<<<(MROWS / 128) * (N3 / 128), 256>>>();
    seq_kernel<<<sms, 256>>>(out);
}

// round 9
// speedup vs baseline: 1.2269x; 1.2269x over previous
#include <cuda_runtime.h>
#include <cuda_bf16.h>
#include <mma.h>
#include <cstdint>

using namespace nvcuda;

#define T_STEPS 512
#define BATCH   64
#define DIN     1024
#define HID     1024
#define N3      3072   // [z | r | c] precomputed x-projections
#define MROWS   (T_STEPS * BATCH)   // 32768

// ---------------- static device scratch (no runtime allocation) ----------------
__device__ float g_P[(size_t)MROWS * N3];               // 384 MB: x-projections (fp32)
__device__ __nv_bfloat16 g_Xh[(size_t)MROWS * DIN];     // X hi (bf16)
__device__ __nv_bfloat16 g_Xl[(size_t)MROWS * DIN];     // X lo
__device__ __nv_bfloat16 g_Bh[(size_t)N3 * DIN];        // phase-1 W rows [n][k] hi
__device__ __nv_bfloat16 g_Bl[(size_t)N3 * DIN];        // phase-1 W rows [n][k] lo
__device__ __nv_bfloat16 g_WAh[2048 * 1024];            // Wfc h-part rows [n][k] hi
__device__ __nv_bfloat16 g_WAl[2048 * 1024];            // lo
__device__ __nv_bfloat16 g_WBh[1024 * 1024];            // Wfc2 h-part rows [n][k] hi
__device__ __nv_bfloat16 g_WBl[1024 * 1024];            // lo
__device__ float g_hb[BATCH * HID];                     // h fp32 (carried state)
__device__ __nv_bfloat16 g_hbh[BATCH * HID];            // h hi
__device__ __nv_bfloat16 g_hbl[BATCH * HID];            // h lo
__device__ float g_PA[8 * BATCH * 2048];                // split-K partials stage A
__device__ float g_PB[16 * BATCH * HID];                // split-K partials stage B
__device__ volatile unsigned g_bar;                     // grid barrier counter

// ---------------- init ----------------
__global__ void init_kernel() {
    int i = blockIdx.x * blockDim.x + threadIdx.x;
    if (i == 0) g_bar = 0u;
    if (i < HID * BATCH) {
        float h0 = 1e-9f;
        g_hb[i] = h0;
        __nv_bfloat16 hh = __float2bfloat16(h0);
        g_hbh[i] = hh;
        g_hbl[i] = __float2bfloat16(h0 - __bfloat162float(hh));
    }
}

// ---------------- convert: fp32 -> bf16 hi/lo for X and all weight views ----------------
__global__ void convert_kernel(const float* __restrict__ x,
                               const float* __restrict__ Wfc,
                               const float* __restrict__ Wfc2) {
    int i = blockIdx.x * blockDim.x + threadIdx.x;
    const size_t NX = (size_t)MROWS * DIN;
    if ((size_t)i < NX) {
        float a = x[i];
        __nv_bfloat16 h = __float2bfloat16(a);
        g_Xh[i] = h;
        g_Xl[i] = __float2bfloat16(a - __bfloat162float(h));
    }
    if (i < N3 * DIN) {            // phase-1 weights: x-part rows
        int n = i >> 10, k = i & 1023;
        float a = (n < 2048) ? Wfc[(size_t)n * 2048 + k]
                             : Wfc2[(size_t)(n - 2048) * 2048 + k];
        __nv_bfloat16 h = __float2bfloat16(a);
        g_Bh[i] = h;
        g_Bl[i] = __float2bfloat16(a - __bfloat162float(h));
    }
    if (i < 2048 * 1024) {         // Wfc h-part rows
        int n = i >> 10, k = i & 1023;
        float a = Wfc[(size_t)n * 2048 + 1024 + k];
        __nv_bfloat16 h = __float2bfloat16(a);
        g_WAh[i] = h;
        g_WAl[i] = __float2bfloat16(a - __bfloat162float(h));
    }
    if (i < 1024 * 1024) {         // Wfc2 h-part rows
        int n = i >> 10, k = i & 1023;
        float a = Wfc2[(size_t)n * 2048 + 1024 + k];
        __nv_bfloat16 h = __float2bfloat16(a);
        g_WBh[i] = h;
        g_WBl[i] = __float2bfloat16(a - __bfloat162float(h));
    }
}

// ---------------- phase 1 (WMMA bf16 hi/lo split, reg double-buffer): P = X @ W^T ----------------
#define LDT 40

__global__ void __launch_bounds__(256) gemm_p_wmma_kernel() {
    __shared__ __nv_bfloat16 Ah[128][LDT];
    __shared__ __nv_bfloat16 Al[128][LDT];
    __shared__ __nv_bfloat16 Bh[128][LDT];
    __shared__ __nv_bfloat16 Bl[128][LDT];

    const int tid = threadIdx.x, wid = tid >> 5;
    const int m0 = (blockIdx.x / 24) << 7;
    const int n0 = (blockIdx.x % 24) << 7;
    const int wm = (wid >> 2) << 6;
    const int wn = (wid & 3) << 5;

    wmma::fragment<wmma::accumulator, 16, 16, 16, float> acc[4][2];
#pragma unroll
    for (int i = 0; i < 4; i++)
#pragma unroll
        for (int j = 0; j < 2; j++) wmma::fill_fragment(acc[i][j], 0.0f);

    // chunk 0 direct load
#pragma unroll
    for (int i = tid; i < 512; i += 256) {
        int r = i >> 2, c = (i & 3) << 3;
        *(uint4*)&Ah[r][c] = *(const uint4*)(g_Xh + (size_t)(m0 + r) * DIN + c);
        *(uint4*)&Al[r][c] = *(const uint4*)(g_Xl + (size_t)(m0 + r) * DIN + c);
        *(uint4*)&Bh[r][c] = *(const uint4*)(g_Bh + (size_t)(n0 + r) * DIN + c);
        *(uint4*)&Bl[r][c] = *(const uint4*)(g_Bl + (size_t)(n0 + r) * DIN + c);
    }
    __syncthreads();

    for (int k0 = 0; k0 < DIN; k0 += 32) {
        const bool nxt = (k0 + 32) < DIN;
        uint4 pxh[2], pxl[2], pwh[2], pwl[2];
        if (nxt) {
#pragma unroll
            for (int ii = 0; ii < 2; ii++) {
                int i = tid + (ii << 8);
                int r = i >> 2, c = (i & 3) << 3;
                pxh[ii] = *(const uint4*)(g_Xh + (size_t)(m0 + r) * DIN + k0 + 32 + c);
                pxl[ii] = *(const uint4*)(g_Xl + (size_t)(m0 + r) * DIN + k0 + 32 + c);
                pwh[ii] = *(const uint4*)(g_Bh + (size_t)(n0 + r) * DIN + k0 + 32 + c);
                pwl[ii] = *(const uint4*)(g_Bl + (size_t)(n0 + r) * DIN + k0 + 32 + c);
            }
        }
#pragma unroll
        for (int kk = 0; kk < 32; kk += 16) {
            wmma::fragment<wmma::matrix_a, 16, 16, 16, __nv_bfloat16, wmma::row_major> fah[4], fal[4];
            wmma::fragment<wmma::matrix_b, 16, 16, 16, __nv_bfloat16, wmma::col_major> fbh[2], fbl[2];
#pragma unroll
            for (int i = 0; i < 4; i++) {
                wmma::load_matrix_sync(fah[i], &Ah[wm + i * 16][kk], LDT);
                wmma::load_matrix_sync(fal[i], &Al[wm + i * 16][kk], LDT);
            }
#pragma unroll
            for (int j = 0; j < 2; j++) {
                wmma::load_matrix_sync(fbh[j], &Bh[wn + j * 16][kk], LDT);
                wmma::load_matrix_sync(fbl[j], &Bl[wn + j * 16][kk], LDT);
            }
#pragma unroll
            for (int i = 0; i < 4; i++)
#pragma unroll
                for (int j = 0; j < 2; j++) {
                    wmma::mma_sync(acc[i][j], fah[i], fbh[j], acc[i][j]);
                    wmma::mma_sync(acc[i][j], fah[i], fbl[j], acc[i][j]);
                    wmma::mma_sync(acc[i][j], fal[i], fbh[j], acc[i][j]);
                }
        }
        __syncthreads();
        if (nxt) {
#pragma unroll
            for (int ii = 0; ii < 2; ii++) {
                int i = tid + (ii << 8);
                int r = i >> 2, c = (i & 3) << 3;
                *(uint4*)&Ah[r][c] = pxh[ii];
                *(uint4*)&Al[r][c] = pxl[ii];
                *(uint4*)&Bh[r][c] = pwh[ii];
                *(uint4*)&Bl[r][c] = pwl[ii];
            }
            __syncthreads();
        }
    }
#pragma unroll
    for (int i = 0; i < 4; i++)
#pragma unroll
        for (int j = 0; j < 2; j++)
            wmma::store_matrix_sync(
                g_P + (size_t)(m0 + wm + i * 16) * N3 + n0 + wn + j * 16,
                acc[i][j], N3, wmma::mem_row_major);
}

// ---------------- robust grid barrier (monotonic counter) ----------------
__device__ __forceinline__ void grid_bar(unsigned target) {
    __threadfence();
    __syncthreads();
    if (threadIdx.x == 0) {
        atomicAdd((unsigned*)&g_bar, 1u);
        while (g_bar < target) __nanosleep(64);
        __threadfence();
    }
    __syncthreads();
}

// ---------------- persistent sequential kernel (512 thr, WMMA, reg double-buffer) ----------------
__global__ void __launch_bounds__(512, 1) seq_kernel(float* __restrict__ out) {
    __shared__ __nv_bfloat16 sAh[64][40];
    __shared__ __nv_bfloat16 sAl[64][40];
    __shared__ __nv_bfloat16 sBh[128][40];
    __shared__ __nv_bfloat16 sBl[128][40];

    const int tid = threadIdx.x, bid = blockIdx.x, nb = gridDim.x;
    const int wid = tid >> 5;
    const int gtid = bid * 512 + tid, nthr = nb * 512;
    const int wm = (wid >> 2) << 4;   // warp row: 0,16,32,48
    const int wn = (wid & 3) << 5;    // warp col: 0,32,64,96
    const int rA = tid >> 2, cA = (tid & 3) << 3;   // A-tile loader (tid<256)
    const int rB = tid >> 2, cB = (tid & 3) << 3;   // B-tile loader (all 512)
    unsigned bar_t = 0;

    for (int t = 0; t < T_STEPS; t++) {
        const float* Pt = g_P + (size_t)t * (BATCH * N3);

        // ======== stage A: PA[kc] = h @ WA^T  (8 kc x 16 ct = 128 units, 64x128 @K=128)
        for (int u = bid; u < 128; u += nb) {
            const int kc = u >> 4, ct = u & 15;
            const int k0 = kc << 7, n0 = ct << 7;

            wmma::fragment<wmma::accumulator, 16, 16, 16, float> acc[2];
            wmma::fill_fragment(acc[0], 0.0f);
            wmma::fill_fragment(acc[1], 0.0f);

            // chunk 0 direct
            if (tid < 256) {
                *(uint4*)&sAh[rA][cA] = __ldcg((const uint4*)(g_hbh + (size_t)rA * HID + k0 + cA));
                *(uint4*)&sAl[rA][cA] = __ldcg((const uint4*)(g_hbl + (size_t)rA * HID + k0 + cA));
            }
            *(uint4*)&sBh[rB][cB] = *(const uint4*)(g_WAh + (size_t)(n0 + rB) * 1024 + k0 + cB);
            *(uint4*)&sBl[rB][cB] = *(const uint4*)(g_WAl + (size_t)(n0 + rB) * 1024 + k0 + cB);
            __syncthreads();

            for (int cc = 0; cc < 128; cc += 32) {
                const bool nxt = (cc + 32) < 128;
                uint4 pah, pal, pbh, pbl;
                if (nxt) {
                    if (tid < 256) {
                        pah = __ldcg((const uint4*)(g_hbh + (size_t)rA * HID + k0 + cc + 32 + cA));
                        pal = __ldcg((const uint4*)(g_hbl + (size_t)rA * HID + k0 + cc + 32 + cA));
                    }
                    pbh = *(const uint4*)(g_WAh + (size_t)(n0 + rB) * 1024 + k0 + cc + 32 + cB);
                    pbl = *(const uint4*)(g_WAl + (size_t)(n0 + rB) * 1024 + k0 + cc + 32 + cB);
                }
#pragma unroll
                for (int kk = 0; kk < 32; kk += 16) {
                    wmma::fragment<wmma::matrix_a, 16, 16, 16, __nv_bfloat16, wmma::row_major> fah, fal;
                    wmma::fragment<wmma::matrix_b, 16, 16, 16, __nv_bfloat16, wmma::col_major> fbh[2], fbl[2];
                    wmma::load_matrix_sync(fah, &sAh[wm][kk], 40);
                    wmma::load_matrix_sync(fal, &sAl[wm][kk], 40);
#pragma unroll
                    for (int j = 0; j < 2; j++) {
                        wmma::load_matrix_sync(fbh[j], &sBh[wn + j * 16][kk], 40);
                        wmma::load_matrix_sync(fbl[j], &sBl[wn + j * 16][kk], 40);
                    }
#pragma unroll
                    for (int j = 0; j < 2; j++) {
                        wmma::mma_sync(acc[j], fah, fbh[j], acc[j]);
                        wmma::mma_sync(acc[j], fah, fbl[j], acc[j]);
                        wmma::mma_sync(acc[j], fal, fbh[j], acc[j]);
                    }
                }
                __syncthreads();
                if (nxt) {
                    if (tid < 256) {
                        *(uint4*)&sAh[rA][cA] = pah;
                        *(uint4*)&sAl[rA][cA] = pal;
                    }
                    *(uint4*)&sBh[rB][cB] = pbh;
                    *(uint4*)&sBl[rB][cB] = pbl;
                    __syncthreads();
                }
            }
#pragma unroll
            for (int j = 0; j < 2; j++)
                wmma::store_matrix_sync(
                    g_PA + (size_t)kc * (BATCH * 2048) + (size_t)wm * 2048 + n0 + wn + j * 16,
                    acc[j], 2048, wmma::mem_row_major);
        }
        bar_t += nb; grid_bar(bar_t);

        // ======== stage B: fused r-reduce + (r*h) @ WB^T  (16 kc x 8 ct = 128 units, 64x128 @K=64)
        for (int u = bid; u < 128; u += nb) {
            const int kc = u >> 3, ct = u & 7;
            const int ks0 = kc << 6, n0 = ct << 7;

            wmma::fragment<wmma::accumulator, 16, 16, 16, float> acc[2];
            wmma::fill_fragment(acc[0], 0.0f);
            wmma::fill_fragment(acc[1], 0.0f);

            // chunk 0: prologue + B load
#pragma unroll
            for (int idx = tid; idx < 2048; idx += 512) {
                int kl = idx & 31, b = idx >> 5;
                int k = ks0 + kl;
                float s = Pt[b * N3 + 1024 + k];
#pragma unroll
                for (int c = 0; c < 8; c++)
                    s += __ldcg(&g_PA[c * (BATCH * 2048) + b * 2048 + 1024 + k]);
                float r = 1.0f / (1.0f + __expf(-s));
                float rh = r * __ldcg(&g_hb[(b << 10) + k]);
                __nv_bfloat16 hi = __float2bfloat16(rh);
                sAh[b][kl] = hi;
                sAl[b][kl] = __float2bfloat16(rh - __bfloat162float(hi));
            }
            *(uint4*)&sBh[rB][cB] = *(const uint4*)(g_WBh + (size_t)(n0 + rB) * 1024 + ks0 + cB);
            *(uint4*)&sBl[rB][cB] = *(const uint4*)(g_WBl + (size_t)(n0 + rB) * 1024 + ks0 + cB);
            __syncthreads();

            for (int cc = 0; cc < 64; cc += 32) {
                const bool nxt = (cc + 32) < 64;
                uint4 pbh, pbl;
                if (nxt) {
                    pbh = *(const uint4*)(g_WBh + (size_t)(n0 + rB) * 1024 + ks0 + cc + 32 + cB);
                    pbl = *(const uint4*)(g_WBl + (size_t)(n0 + rB) * 1024 + ks0 + cc + 32 + cB);
                }
#pragma unroll
                for (int kk = 0; kk < 32; kk += 16) {
                    wmma::fragment<wmma::matrix_a, 16, 16, 16, __nv_bfloat16, wmma::row_major> fah, fal;
                    wmma::fragment<wmma::matrix_b, 16, 16, 16, __nv_bfloat16, wmma::col_major> fbh[2], fbl[2];
                    wmma::load_matrix_sync(fah, &sAh[wm][kk], 40);
                    wmma::load_matrix_sync(fal, &sAl[wm][kk], 40);
#pragma unroll
                    for (int j = 0; j < 2; j++) {
                        wmma::load_matrix_sync(fbh[j], &sBh[wn + j * 16][kk], 40);
                        wmma::load_matrix_sync(fbl[j], &sBl[wn + j * 16][kk], 40);
                    }
#pragma unroll
                    for (int j = 0; j < 2; j++) {
                        wmma::mma_sync(acc[j], fah, fbh[j], acc[j]);
                        wmma::mma_sync(acc[j], fah, fbl[j], acc[j]);
                        wmma::mma_sync(acc[j], fal, fbh[j], acc[j]);
                    }
                }
                __syncthreads();
                if (nxt) {
                    *(uint4*)&sBh[rB][cB] = pbh;
                    *(uint4*)&sBl[rB][cB] = pbl;
                    // prologue for next chunk
#pragma unroll
                    for (int idx = tid; idx < 2048; idx += 512) {
                        int kl = idx & 31, b = idx >> 5;
                        int k = ks0 + cc + 32 + kl;
                        float s = Pt[b * N3 + 1024 + k];
#pragma unroll
                        for (int c = 0; c < 8; c++)
                            s += __ldcg(&g_PA[c * (BATCH * 2048) + b * 2048 + 1024 + k]);
                        float r = 1.0f / (1.0f + __expf(-s));
                        float rh = r * __ldcg(&g_hb[(b << 10) + k]);
                        __nv_bfloat16 hi = __float2bfloat16(rh);
                        sAh[b][kl] = hi;
                        sAl[b][kl] = __float2bfloat16(rh - __bfloat162float(hi));
                    }
                    __syncthreads();
                }
            }
#pragma unroll
            for (int j = 0; j < 2; j++)
                wmma::store_matrix_sync(
                    g_PB + (size_t)kc * (BATCH * 1024) + (size_t)wm * 1024 + n0 + wn + j * 16,
                    acc[j], 1024, wmma::mem_row_major);
        }
        bar_t += nb; grid_bar(bar_t);

        // ======== stage C: z reduce + tanh(c) + blend + h update (+ bf16 mirror) + output
        float* ot = out + (size_t)t * (BATCH * HID);
        for (int o = gtid; o < BATCH * HID; o += nthr) {
            int b = o >> 10, j = o & 1023;
            float sz = Pt[b * N3 + j];
#pragma unroll
            for (int c = 0; c < 8; c++)
                sz += __ldcg(&g_PA[c * (BATCH * 2048) + b * 2048 + j]);
            float z = 1.0f / (1.0f + __expf(-sz));

            float sc = Pt[b * N3 + 2048 + j];
#pragma unroll
            for (int c = 0; c < 16; c++)
                sc += __ldcg(&g_PB[c * (BATCH * 1024) + o]);
            float cv = tanhf(sc);

            float hcur = __ldcg(&g_hb[o]);
            float hn = fmaf(z, cv - hcur, hcur);   // (1-z)*h + z*c
            ot[o] = hn;
            g_hb[o] = hn;
            __nv_bfloat16 hh = __float2bfloat16(hn);
            g_hbh[o] = hh;
            g_hbl[o] = __float2bfloat16(hn - __bfloat162float(hh));
        }
        bar_t += nb; grid_bar(bar_t);
    }
}

// ---------------- launch (4 graph nodes total) ----------------
extern "C" void kernel_launch(void* const* d_in, const int* in_sizes, int n_in,
                              void* d_out, int out_size) {
    const float* x    = (const float*)d_in[0];   // [512, 64, 1024]
    const float* Wfc  = (const float*)d_in[1];   // [2048, 2048]
    const float* Wfc2 = (const float*)d_in[2];   // [1024, 2048]
    // d_in[3] (w_hh), d_in[4] (bias): dead — delta_u never reaches the output
    float* out = (float*)d_out;                  // [512, 64, 1024]

    int sms = 148;
    cudaDeviceGetAttribute(&sms, cudaDevAttrMultiProcessorCount, 0);
    if (sms > 148) sms = 148;

    init_kernel<<<256, 256>>>();
    convert_kernel<<<(MROWS * DIN + 255) / 256, 256>>>(x, Wfc, Wfc2);
    gemm_p_wmma_kernel<<<(MROWS / 128) * (N3 / 128), 256>>>();
    seq_kernel<<<sms, 512>>>(out);
}

// round 10
// speedup vs baseline: 1.4171x; 1.1551x over previous
#include <cuda_runtime.h>
#include <cuda_bf16.h>
#include <mma.h>
#include <cstdint>

using namespace nvcuda;

#define T_STEPS 512
#define BATCH   64
#define DIN     1024
#define HID     1024
#define N3      3072   // [z | r | c] precomputed x-projections
#define MROWS   (T_STEPS * BATCH)   // 32768

// ---------------- static device scratch (no runtime allocation) ----------------
__device__ float g_P[(size_t)MROWS * N3];               // 384 MB: x-projections (fp32)
__device__ __nv_bfloat16 g_Xh[(size_t)MROWS * DIN];     // X hi (bf16)
__device__ __nv_bfloat16 g_Xl[(size_t)MROWS * DIN];     // X lo
__device__ __nv_bfloat16 g_Bh[(size_t)N3 * DIN];        // phase-1 W rows [n][k] hi
__device__ __nv_bfloat16 g_Bl[(size_t)N3 * DIN];        // phase-1 W rows [n][k] lo
__device__ __nv_bfloat16 g_WAh[2048 * 1024];            // Wfc h-part rows [n][k] hi
__device__ __nv_bfloat16 g_WAl[2048 * 1024];            // lo
__device__ __nv_bfloat16 g_WBh[1024 * 1024];            // Wfc2 h-part rows [n][k] hi
__device__ __nv_bfloat16 g_WBl[1024 * 1024];            // lo
__device__ float g_hb[BATCH * HID];                     // h fp32 (carried state)
__device__ __nv_bfloat16 g_hbh[BATCH * HID];            // h hi
__device__ __nv_bfloat16 g_hbl[BATCH * HID];            // h lo
__device__ float g_PA[8 * BATCH * 2048];                // split-K partials stage A
__device__ float g_PB[16 * BATCH * HID];                // split-K partials stage B
__device__ volatile unsigned g_bar;                     // grid barrier counter

// ---------------- init ----------------
__global__ void init_kernel() {
    int i = blockIdx.x * blockDim.x + threadIdx.x;
    if (i == 0) g_bar = 0u;
    if (i < HID * BATCH) {
        float h0 = 1e-9f;
        g_hb[i] = h0;
        __nv_bfloat16 hh = __float2bfloat16(h0);
        g_hbh[i] = hh;
        g_hbl[i] = __float2bfloat16(h0 - __bfloat162float(hh));
    }
}

// ---------------- convert: fp32 -> bf16 hi/lo for X and all weight views ----------------
__global__ void convert_kernel(const float* __restrict__ x,
                               const float* __restrict__ Wfc,
                               const float* __restrict__ Wfc2) {
    int i = blockIdx.x * blockDim.x + threadIdx.x;
    const size_t NX = (size_t)MROWS * DIN;
    if ((size_t)i < NX) {
        float a = x[i];
        __nv_bfloat16 h = __float2bfloat16(a);
        g_Xh[i] = h;
        g_Xl[i] = __float2bfloat16(a - __bfloat162float(h));
    }
    if (i < N3 * DIN) {            // phase-1 weights: x-part rows
        int n = i >> 10, k = i & 1023;
        float a = (n < 2048) ? Wfc[(size_t)n * 2048 + k]
                             : Wfc2[(size_t)(n - 2048) * 2048 + k];
        __nv_bfloat16 h = __float2bfloat16(a);
        g_Bh[i] = h;
        g_Bl[i] = __float2bfloat16(a - __bfloat162float(h));
    }
    if (i < 2048 * 1024) {         // Wfc h-part rows
        int n = i >> 10, k = i & 1023;
        float a = Wfc[(size_t)n * 2048 + 1024 + k];
        __nv_bfloat16 h = __float2bfloat16(a);
        g_WAh[i] = h;
        g_WAl[i] = __float2bfloat16(a - __bfloat162float(h));
    }
    if (i < 1024 * 1024) {         // Wfc2 h-part rows
        int n = i >> 10, k = i & 1023;
        float a = Wfc2[(size_t)n * 2048 + 1024 + k];
        __nv_bfloat16 h = __float2bfloat16(a);
        g_WBh[i] = h;
        g_WBl[i] = __float2bfloat16(a - __bfloat162float(h));
    }
}

// ---------------- phase 1 (WMMA bf16 hi/lo split, reg double-buffer): P = X @ W^T ----------------
#define LDT 40

__global__ void __launch_bounds__(256) gemm_p_wmma_kernel() {
    __shared__ __nv_bfloat16 Ah[128][LDT];
    __shared__ __nv_bfloat16 Al[128][LDT];
    __shared__ __nv_bfloat16 Bh[128][LDT];
    __shared__ __nv_bfloat16 Bl[128][LDT];

    const int tid = threadIdx.x, wid = tid >> 5;
    const int m0 = (blockIdx.x / 24) << 7;
    const int n0 = (blockIdx.x % 24) << 7;
    const int wm = (wid >> 2) << 6;
    const int wn = (wid & 3) << 5;

    wmma::fragment<wmma::accumulator, 16, 16, 16, float> acc[4][2];
#pragma unroll
    for (int i = 0; i < 4; i++)
#pragma unroll
        for (int j = 0; j < 2; j++) wmma::fill_fragment(acc[i][j], 0.0f);

#pragma unroll
    for (int i = tid; i < 512; i += 256) {
        int r = i >> 2, c = (i & 3) << 3;
        *(uint4*)&Ah[r][c] = *(const uint4*)(g_Xh + (size_t)(m0 + r) * DIN + c);
        *(uint4*)&Al[r][c] = *(const uint4*)(g_Xl + (size_t)(m0 + r) * DIN + c);
        *(uint4*)&Bh[r][c] = *(const uint4*)(g_Bh + (size_t)(n0 + r) * DIN + c);
        *(uint4*)&Bl[r][c] = *(const uint4*)(g_Bl + (size_t)(n0 + r) * DIN + c);
    }
    __syncthreads();

    for (int k0 = 0; k0 < DIN; k0 += 32) {
        const bool nxt = (k0 + 32) < DIN;
        uint4 pxh[2], pxl[2], pwh[2], pwl[2];
        if (nxt) {
#pragma unroll
            for (int ii = 0; ii < 2; ii++) {
                int i = tid + (ii << 8);
                int r = i >> 2, c = (i & 3) << 3;
                pxh[ii] = *(const uint4*)(g_Xh + (size_t)(m0 + r) * DIN + k0 + 32 + c);
                pxl[ii] = *(const uint4*)(g_Xl + (size_t)(m0 + r) * DIN + k0 + 32 + c);
                pwh[ii] = *(const uint4*)(g_Bh + (size_t)(n0 + r) * DIN + k0 + 32 + c);
                pwl[ii] = *(const uint4*)(g_Bl + (size_t)(n0 + r) * DIN + k0 + 32 + c);
            }
        }
#pragma unroll
        for (int kk = 0; kk < 32; kk += 16) {
            wmma::fragment<wmma::matrix_a, 16, 16, 16, __nv_bfloat16, wmma::row_major> fah[4], fal[4];
            wmma::fragment<wmma::matrix_b, 16, 16, 16, __nv_bfloat16, wmma::col_major> fbh[2], fbl[2];
#pragma unroll
            for (int i = 0; i < 4; i++) {
                wmma::load_matrix_sync(fah[i], &Ah[wm + i * 16][kk], LDT);
                wmma::load_matrix_sync(fal[i], &Al[wm + i * 16][kk], LDT);
            }
#pragma unroll
            for (int j = 0; j < 2; j++) {
                wmma::load_matrix_sync(fbh[j], &Bh[wn + j * 16][kk], LDT);
                wmma::load_matrix_sync(fbl[j], &Bl[wn + j * 16][kk], LDT);
            }
#pragma unroll
            for (int i = 0; i < 4; i++)
#pragma unroll
                for (int j = 0; j < 2; j++) {
                    wmma::mma_sync(acc[i][j], fah[i], fbh[j], acc[i][j]);
                    wmma::mma_sync(acc[i][j], fah[i], fbl[j], acc[i][j]);
                    wmma::mma_sync(acc[i][j], fal[i], fbh[j], acc[i][j]);
                }
        }
        __syncthreads();
        if (nxt) {
#pragma unroll
            for (int ii = 0; ii < 2; ii++) {
                int i = tid + (ii << 8);
                int r = i >> 2, c = (i & 3) << 3;
                *(uint4*)&Ah[r][c] = pxh[ii];
                *(uint4*)&Al[r][c] = pxl[ii];
                *(uint4*)&Bh[r][c] = pwh[ii];
                *(uint4*)&Bl[r][c] = pwl[ii];
            }
            __syncthreads();
        }
    }
#pragma unroll
    for (int i = 0; i < 4; i++)
#pragma unroll
        for (int j = 0; j < 2; j++)
            wmma::store_matrix_sync(
                g_P + (size_t)(m0 + wm + i * 16) * N3 + n0 + wn + j * 16,
                acc[i][j], N3, wmma::mem_row_major);
}

// ---------------- robust grid barrier (monotonic counter) ----------------
__device__ __forceinline__ void grid_bar(unsigned target) {
    __threadfence();
    __syncthreads();
    if (threadIdx.x == 0) {
        atomicAdd((unsigned*)&g_bar, 1u);
        while (g_bar < target) __nanosleep(64);
        __threadfence();
    }
    __syncthreads();
}

// ---------------- persistent sequential kernel: weights RESIDENT in smem ----------------
// Block bid owns stage-A unit bid (kcA=bid>>4, ctA=bid&15) and stage-B unit bid
// (kcB=bid>>3, ctB=bid&7) for the whole run. Weight tiles loaded once.
// smem layout (bf16 elems):
//   sWAh[128][136], sWAl[128][136]   stage-A weights (68 KB)
//   sWBh[128][72],  sWBl[128][72]    stage-B weights (36 KB)
//   sHh [64][136],  sHl [64][136]    h / rh tile     (34 KB)
#define WA_PITCH 136
#define WB_PITCH 72
#define SEQ_SMEM_ELEMS (128*WA_PITCH*2 + 128*WB_PITCH*2 + 64*WA_PITCH*2)
#define SEQ_SMEM_BYTES (SEQ_SMEM_ELEMS * 2)   // 141,312 bytes

__global__ void __launch_bounds__(512, 1) seq_kernel(float* __restrict__ out) {
    extern __shared__ __nv_bfloat16 smem[];
    __nv_bfloat16* sWAh = smem;
    __nv_bfloat16* sWAl = sWAh + 128 * WA_PITCH;
    __nv_bfloat16* sWBh = sWAl + 128 * WA_PITCH;
    __nv_bfloat16* sWBl = sWBh + 128 * WB_PITCH;
    __nv_bfloat16* sHh  = sWBl + 128 * WB_PITCH;
    __nv_bfloat16* sHl  = sHh  + 64 * WA_PITCH;

    const int tid = threadIdx.x, bid = blockIdx.x, nb = gridDim.x;
    const int wid = tid >> 5;
    const int gtid = bid * 512 + tid, nthr = nb * 512;
    const int wm = (wid >> 2) << 4;   // warp row: 0,16,32,48
    const int wn = (wid & 3) << 5;    // warp col: 0,32,64,96
    unsigned bar_t = 0;

    const int kcA = bid >> 4, ctA = bid & 15;      // stage-A unit (bid<128)
    const int k0A = kcA << 7, n0A = ctA << 7;
    const int kcB = bid >> 3, ctB = bid & 7;       // stage-B unit (bid<128)
    const int ks0B = kcB << 6, n0B = ctB << 7;

    // ---- one-time weight preload ----
    if (bid < 128) {
        for (int i = tid; i < 2048; i += 512) {        // WA: 128x128 hi/lo
            int r = i >> 4, c = (i & 15) << 3;
            *(uint4*)&sWAh[r * WA_PITCH + c] =
                *(const uint4*)(g_WAh + (size_t)(n0A + r) * 1024 + k0A + c);
            *(uint4*)&sWAl[r * WA_PITCH + c] =
                *(const uint4*)(g_WAl + (size_t)(n0A + r) * 1024 + k0A + c);
        }
        for (int i = tid; i < 1024; i += 512) {        // WB: 128x64 hi/lo
            int r = i >> 3, c = (i & 7) << 3;
            *(uint4*)&sWBh[r * WB_PITCH + c] =
                *(const uint4*)(g_WBh + (size_t)(n0B + r) * 1024 + ks0B + c);
            *(uint4*)&sWBl[r * WB_PITCH + c] =
                *(const uint4*)(g_WBl + (size_t)(n0B + r) * 1024 + ks0B + c);
        }
    }
    __syncthreads();

    for (int t = 0; t < T_STEPS; t++) {
        const float* Pt = g_P + (size_t)t * (BATCH * N3);

        // ======== stage A: PA[kcA] slice = h @ WA^T   (64x128 @K=128, weights resident)
        if (bid < 128) {
            // load h slice 64x128 hi/lo
            for (int i = tid; i < 1024; i += 512) {
                int r = i >> 4, c = (i & 15) << 3;
                *(uint4*)&sHh[r * WA_PITCH + c] =
                    __ldcg((const uint4*)(g_hbh + (size_t)r * HID + k0A + c));
                *(uint4*)&sHl[r * WA_PITCH + c] =
                    __ldcg((const uint4*)(g_hbl + (size_t)r * HID + k0A + c));
            }
            __syncthreads();

            wmma::fragment<wmma::accumulator, 16, 16, 16, float> acc[2];
            wmma::fill_fragment(acc[0], 0.0f);
            wmma::fill_fragment(acc[1], 0.0f);
#pragma unroll
            for (int kk = 0; kk < 128; kk += 16) {
                wmma::fragment<wmma::matrix_a, 16, 16, 16, __nv_bfloat16, wmma::row_major> fah, fal;
                wmma::fragment<wmma::matrix_b, 16, 16, 16, __nv_bfloat16, wmma::col_major> fbh[2], fbl[2];
                wmma::load_matrix_sync(fah, &sHh[wm * WA_PITCH + kk], WA_PITCH);
                wmma::load_matrix_sync(fal, &sHl[wm * WA_PITCH + kk], WA_PITCH);
#pragma unroll
                for (int j = 0; j < 2; j++) {
                    wmma::load_matrix_sync(fbh[j], &sWAh[(wn + j * 16) * WA_PITCH + kk], WA_PITCH);
                    wmma::load_matrix_sync(fbl[j], &sWAl[(wn + j * 16) * WA_PITCH + kk], WA_PITCH);
                }
#pragma unroll
                for (int j = 0; j < 2; j++) {
                    wmma::mma_sync(acc[j], fah, fbh[j], acc[j]);
                    wmma::mma_sync(acc[j], fah, fbl[j], acc[j]);
                    wmma::mma_sync(acc[j], fal, fbh[j], acc[j]);
                }
            }
#pragma unroll
            for (int j = 0; j < 2; j++)
                wmma::store_matrix_sync(
                    g_PA + (size_t)kcA * (BATCH * 2048) + (size_t)wm * 2048 + n0A + wn + j * 16,
                    acc[j], 2048, wmma::mem_row_major);
            __syncthreads();
        }
        bar_t += nb; grid_bar(bar_t);

        // ======== stage B: fused r-reduce + (r*h) @ WB^T   (64x128 @K=64, weights resident)
        if (bid < 128) {
            // prologue: rh = sigmoid(r-sum)*h for k in [ks0B, ks0B+64), all 64 batches
            for (int idx = tid; idx < 4096; idx += 512) {
                int kl = idx & 63, b = idx >> 6;
                int k = ks0B + kl;
                float s = Pt[b * N3 + 1024 + k];
#pragma unroll
                for (int c = 0; c < 8; c++)
                    s += __ldcg(&g_PA[c * (BATCH * 2048) + b * 2048 + 1024 + k]);
                float r = 1.0f / (1.0f + __expf(-s));
                float rh = r * __ldcg(&g_hb[(b << 10) + k]);
                __nv_bfloat16 hi = __float2bfloat16(rh);
                sHh[b * WA_PITCH + kl] = hi;
                sHl[b * WA_PITCH + kl] = __float2bfloat16(rh - __bfloat162float(hi));
            }
            __syncthreads();

            wmma::fragment<wmma::accumulator, 16, 16, 16, float> acc[2];
            wmma::fill_fragment(acc[0], 0.0f);
            wmma::fill_fragment(acc[1], 0.0f);
#pragma unroll
            for (int kk = 0; kk < 64; kk += 16) {
                wmma::fragment<wmma::matrix_a, 16, 16, 16, __nv_bfloat16, wmma::row_major> fah, fal;
                wmma::fragment<wmma::matrix_b, 16, 16, 16, __nv_bfloat16, wmma::col_major> fbh[2], fbl[2];
                wmma::load_matrix_sync(fah, &sHh[wm * WA_PITCH + kk], WA_PITCH);
                wmma::load_matrix_sync(fal, &sHl[wm * WA_PITCH + kk], WA_PITCH);
#pragma unroll
                for (int j = 0; j < 2; j++) {
                    wmma::load_matrix_sync(fbh[j], &sWBh[(wn + j * 16) * WB_PITCH + kk], WB_PITCH);
                    wmma::load_matrix_sync(fbl[j], &sWBl[(wn + j * 16) * WB_PITCH + kk], WB_PITCH);
                }
#pragma unroll
                for (int j = 0; j < 2; j++) {
                    wmma::mma_sync(acc[j], fah, fbh[j], acc[j]);
                    wmma::mma_sync(acc[j], fah, fbl[j], acc[j]);
                    wmma::mma_sync(acc[j], fal, fbh[j], acc[j]);
                }
            }
#pragma unroll
            for (int j = 0; j < 2; j++)
                wmma::store_matrix_sync(
                    g_PB + (size_t)kcB * (BATCH * 1024) + (size_t)wm * 1024 + n0B + wn + j * 16,
                    acc[j], 1024, wmma::mem_row_major);
            __syncthreads();
        }
        bar_t += nb; grid_bar(bar_t);

        // ======== stage C: z reduce + tanh(c) + blend + h update (+ bf16 mirror) + output
        float* ot = out + (size_t)t * (BATCH * HID);
        for (int o = gtid; o < BATCH * HID; o += nthr) {
            int b = o >> 10, j = o & 1023;
            float sz = Pt[b * N3 + j];
#pragma unroll
            for (int c = 0; c < 8; c++)
                sz += __ldcg(&g_PA[c * (BATCH * 2048) + b * 2048 + j]);
            float z = 1.0f / (1.0f + __expf(-sz));

            float sc = Pt[b * N3 + 2048 + j];
#pragma unroll
            for (int c = 0; c < 16; c++)
                sc += __ldcg(&g_PB[c * (BATCH * 1024) + o]);
            float cv = tanhf(sc);

            float hcur = __ldcg(&g_hb[o]);
            float hn = fmaf(z, cv - hcur, hcur);   // (1-z)*h + z*c
            ot[o] = hn;
            g_hb[o] = hn;
            __nv_bfloat16 hh = __float2bfloat16(hn);
            g_hbh[o] = hh;
            g_hbl[o] = __float2bfloat16(hn - __bfloat162float(hh));
        }
        bar_t += nb; grid_bar(bar_t);
    }
}

// ---------------- launch (4 graph nodes total) ----------------
extern "C" void kernel_launch(void* const* d_in, const int* in_sizes, int n_in,
                              void* d_out, int out_size) {
    const float* x    = (const float*)d_in[0];   // [512, 64, 1024]
    const float* Wfc  = (const float*)d_in[1];   // [2048, 2048]
    const float* Wfc2 = (const float*)d_in[2];   // [1024, 2048]
    // d_in[3] (w_hh), d_in[4] (bias): dead — delta_u never reaches the output
    float* out = (float*)d_out;                  // [512, 64, 1024]

    int sms = 148;
    cudaDeviceGetAttribute(&sms, cudaDevAttrMultiProcessorCount, 0);
    if (sms > 148) sms = 148;

    // One-time dynamic-smem opt-in; never executed during graph capture
    // (first kernel_launch call is the uncaptured correctness run).
    static bool attr_done = false;
    if (!attr_done) {
        cudaFuncSetAttribute(seq_kernel,
                             cudaFuncAttributeMaxDynamicSharedMemorySize, SEQ_SMEM_BYTES);
        attr_done = true;
    }

    init_kernel<<<256, 256>>>();
    convert_kernel<<<(MROWS * DIN + 255) / 256, 256>>>(x, Wfc, Wfc2);
    gemm_p_wmma_kernel<<<(MROWS / 128) * (N3 / 128), 256>>>();
    seq_kernel<<<sms, 512, SEQ_SMEM_BYTES>>>(out);
}

// round 11
// speedup vs baseline: 1.5446x; 1.0900x over previous
#include <cuda_runtime.h>
#include <cuda_bf16.h>
#include <mma.h>
#include <cstdint>

using namespace nvcuda;

#define T_STEPS 512
#define BATCH   64
#define DIN     1024
#define HID     1024
#define N3      3072   // [z | r | c] precomputed x-projections
#define MROWS   (T_STEPS * BATCH)   // 32768

// ---------------- static device scratch (no runtime allocation) ----------------
__device__ float g_P[(size_t)MROWS * N3];               // 384 MB: x-projections (fp32)
__device__ __nv_bfloat16 g_Xh[(size_t)MROWS * DIN];     // X hi (bf16)
__device__ __nv_bfloat16 g_Xl[(size_t)MROWS * DIN];     // X lo
__device__ __nv_bfloat16 g_Bh[(size_t)N3 * DIN];        // phase-1 W rows [n][k] hi
__device__ __nv_bfloat16 g_Bl[(size_t)N3 * DIN];        // phase-1 W rows [n][k] lo
__device__ __nv_bfloat16 g_WAh[2048 * 1024];            // Wfc h-part rows [n][k] hi
__device__ __nv_bfloat16 g_WAl[2048 * 1024];            // lo
__device__ __nv_bfloat16 g_WBh[1024 * 1024];            // Wfc2 h-part rows [n][k] hi
__device__ __nv_bfloat16 g_WBl[1024 * 1024];            // lo
__device__ float g_hb[BATCH * HID];                     // h fp32 (carried state)
__device__ __nv_bfloat16 g_hbh[BATCH * HID];            // h hi
__device__ __nv_bfloat16 g_hbl[BATCH * HID];            // h lo
__device__ float g_PA[8 * BATCH * 2048];                // split-K partials stage A
__device__ float g_PB[16 * BATCH * HID];                // split-K partials stage B
__device__ unsigned g_bar;                              // grid barrier counter

// ---------------- init ----------------
__global__ void init_kernel() {
    int i = blockIdx.x * blockDim.x + threadIdx.x;
    if (i == 0) g_bar = 0u;
    if (i < HID * BATCH) {
        float h0 = 1e-9f;
        g_hb[i] = h0;
        __nv_bfloat16 hh = __float2bfloat16(h0);
        g_hbh[i] = hh;
        g_hbl[i] = __float2bfloat16(h0 - __bfloat162float(hh));
    }
}

// ---------------- convert: fp32 -> bf16 hi/lo for X and all weight views ----------------
__global__ void convert_kernel(const float* __restrict__ x,
                               const float* __restrict__ Wfc,
                               const float* __restrict__ Wfc2) {
    int i = blockIdx.x * blockDim.x + threadIdx.x;
    const size_t NX = (size_t)MROWS * DIN;
    if ((size_t)i < NX) {
        float a = x[i];
        __nv_bfloat16 h = __float2bfloat16(a);
        g_Xh[i] = h;
        g_Xl[i] = __float2bfloat16(a - __bfloat162float(h));
    }
    if (i < N3 * DIN) {            // phase-1 weights: x-part rows
        int n = i >> 10, k = i & 1023;
        float a = (n < 2048) ? Wfc[(size_t)n * 2048 + k]
                             : Wfc2[(size_t)(n - 2048) * 2048 + k];
        __nv_bfloat16 h = __float2bfloat16(a);
        g_Bh[i] = h;
        g_Bl[i] = __float2bfloat16(a - __bfloat162float(h));
    }
    if (i < 2048 * 1024) {         // Wfc h-part rows
        int n = i >> 10, k = i & 1023;
        float a = Wfc[(size_t)n * 2048 + 1024 + k];
        __nv_bfloat16 h = __float2bfloat16(a);
        g_WAh[i] = h;
        g_WAl[i] = __float2bfloat16(a - __bfloat162float(h));
    }
    if (i < 1024 * 1024) {         // Wfc2 h-part rows
        int n = i >> 10, k = i & 1023;
        float a = Wfc2[(size_t)n * 2048 + 1024 + k];
        __nv_bfloat16 h = __float2bfloat16(a);
        g_WBh[i] = h;
        g_WBl[i] = __float2bfloat16(a - __bfloat162float(h));
    }
}

// ---------------- phase 1 (WMMA bf16 hi/lo split, reg double-buffer): P = X @ W^T ----------------
#define LDT 40

__global__ void __launch_bounds__(256) gemm_p_wmma_kernel() {
    __shared__ __nv_bfloat16 Ah[128][LDT];
    __shared__ __nv_bfloat16 Al[128][LDT];
    __shared__ __nv_bfloat16 Bh[128][LDT];
    __shared__ __nv_bfloat16 Bl[128][LDT];

    const int tid = threadIdx.x, wid = tid >> 5;
    const int m0 = (blockIdx.x / 24) << 7;
    const int n0 = (blockIdx.x % 24) << 7;
    const int wm = (wid >> 2) << 6;
    const int wn = (wid & 3) << 5;

    wmma::fragment<wmma::accumulator, 16, 16, 16, float> acc[4][2];
#pragma unroll
    for (int i = 0; i < 4; i++)
#pragma unroll
        for (int j = 0; j < 2; j++) wmma::fill_fragment(acc[i][j], 0.0f);

#pragma unroll
    for (int i = tid; i < 512; i += 256) {
        int r = i >> 2, c = (i & 3) << 3;
        *(uint4*)&Ah[r][c] = *(const uint4*)(g_Xh + (size_t)(m0 + r) * DIN + c);
        *(uint4*)&Al[r][c] = *(const uint4*)(g_Xl + (size_t)(m0 + r) * DIN + c);
        *(uint4*)&Bh[r][c] = *(const uint4*)(g_Bh + (size_t)(n0 + r) * DIN + c);
        *(uint4*)&Bl[r][c] = *(const uint4*)(g_Bl + (size_t)(n0 + r) * DIN + c);
    }
    __syncthreads();

    for (int k0 = 0; k0 < DIN; k0 += 32) {
        const bool nxt = (k0 + 32) < DIN;
        uint4 pxh[2], pxl[2], pwh[2], pwl[2];
        if (nxt) {
#pragma unroll
            for (int ii = 0; ii < 2; ii++) {
                int i = tid + (ii << 8);
                int r = i >> 2, c = (i & 3) << 3;
                pxh[ii] = *(const uint4*)(g_Xh + (size_t)(m0 + r) * DIN + k0 + 32 + c);
                pxl[ii] = *(const uint4*)(g_Xl + (size_t)(m0 + r) * DIN + k0 + 32 + c);
                pwh[ii] = *(const uint4*)(g_Bh + (size_t)(n0 + r) * DIN + k0 + 32 + c);
                pwl[ii] = *(const uint4*)(g_Bl + (size_t)(n0 + r) * DIN + k0 + 32 + c);
            }
        }
#pragma unroll
        for (int kk = 0; kk < 32; kk += 16) {
            wmma::fragment<wmma::matrix_a, 16, 16, 16, __nv_bfloat16, wmma::row_major> fah[4], fal[4];
            wmma::fragment<wmma::matrix_b, 16, 16, 16, __nv_bfloat16, wmma::col_major> fbh[2], fbl[2];
#pragma unroll
            for (int i = 0; i < 4; i++) {
                wmma::load_matrix_sync(fah[i], &Ah[wm + i * 16][kk], LDT);
                wmma::load_matrix_sync(fal[i], &Al[wm + i * 16][kk], LDT);
            }
#pragma unroll
            for (int j = 0; j < 2; j++) {
                wmma::load_matrix_sync(fbh[j], &Bh[wn + j * 16][kk], LDT);
                wmma::load_matrix_sync(fbl[j], &Bl[wn + j * 16][kk], LDT);
            }
#pragma unroll
            for (int i = 0; i < 4; i++)
#pragma unroll
                for (int j = 0; j < 2; j++) {
                    wmma::mma_sync(acc[i][j], fah[i], fbh[j], acc[i][j]);
                    wmma::mma_sync(acc[i][j], fah[i], fbl[j], acc[i][j]);
                    wmma::mma_sync(acc[i][j], fal[i], fbh[j], acc[i][j]);
                }
        }
        __syncthreads();
        if (nxt) {
#pragma unroll
            for (int ii = 0; ii < 2; ii++) {
                int i = tid + (ii << 8);
                int r = i >> 2, c = (i & 3) << 3;
                *(uint4*)&Ah[r][c] = pxh[ii];
                *(uint4*)&Al[r][c] = pxl[ii];
                *(uint4*)&Bh[r][c] = pwh[ii];
                *(uint4*)&Bl[r][c] = pwl[ii];
            }
            __syncthreads();
        }
    }
#pragma unroll
    for (int i = 0; i < 4; i++)
#pragma unroll
        for (int j = 0; j < 2; j++)
            wmma::store_matrix_sync(
                g_P + (size_t)(m0 + wm + i * 16) * N3 + n0 + wn + j * 16,
                acc[i][j], N3, wmma::mem_row_major);
}

// ---------------- grid barrier: CG-style release/acquire (NO L1-flushing fences) ----------------
// All cross-step mutable reads in seq_kernel use __ldcg (L2), so we only need
// store->L2 ordering (red.release) and load ordering (ld.acquire), exactly as
// cooperative_groups::grid_group::sync() does. Avoids CCTL.IVALL entirely.
__device__ __forceinline__ void grid_bar(unsigned target) {
    __syncthreads();                      // block arrival + cta-scope ordering
    if (threadIdx.x == 0) {
        unsigned* bar = &g_bar;
        asm volatile("red.release.gpu.add.u32 [%0], %1;" :: "l"(bar), "r"(1u) : "memory");
        unsigned v;
        do {
            asm volatile("ld.acquire.gpu.u32 %0, [%1];" : "=r"(v) : "l"(bar) : "memory");
        } while (v < target);
    }
    __syncthreads();                      // broadcast release to whole block
}

// ---------------- persistent sequential kernel: weights RESIDENT in smem ----------------
// grid = 128 blocks: every block owns stage-A unit bid and stage-B unit bid.
// smem layout (bf16): sWAh/sWAl 128x136, sWBh/sWBl 128x72, sHh/sHl 64x136.
#define WA_PITCH 136
#define WB_PITCH 72
#define SEQ_SMEM_ELEMS (128*WA_PITCH*2 + 128*WB_PITCH*2 + 64*WA_PITCH*2)
#define SEQ_SMEM_BYTES (SEQ_SMEM_ELEMS * 2)   // 141,312 bytes
#define NBLK 128

__global__ void __launch_bounds__(512, 1) seq_kernel(float* __restrict__ out) {
    extern __shared__ __nv_bfloat16 smem[];
    __nv_bfloat16* sWAh = smem;
    __nv_bfloat16* sWAl = sWAh + 128 * WA_PITCH;
    __nv_bfloat16* sWBh = sWAl + 128 * WA_PITCH;
    __nv_bfloat16* sWBl = sWBh + 128 * WB_PITCH;
    __nv_bfloat16* sHh  = sWBl + 128 * WB_PITCH;
    __nv_bfloat16* sHl  = sHh  + 64 * WA_PITCH;

    const int tid = threadIdx.x, bid = blockIdx.x;
    const int wid = tid >> 5;
    const int gtid = bid * 512 + tid;          // 0..65535 exactly covers BATCH*HID
    const int wm = (wid >> 2) << 4;   // warp row: 0,16,32,48
    const int wn = (wid & 3) << 5;    // warp col: 0,32,64,96
    unsigned bar_t = 0;

    const int kcA = bid >> 4, ctA = bid & 15;      // stage-A unit
    const int k0A = kcA << 7, n0A = ctA << 7;
    const int kcB = bid >> 3, ctB = bid & 7;       // stage-B unit
    const int ks0B = kcB << 6, n0B = ctB << 7;

    // ---- one-time weight preload ----
    for (int i = tid; i < 2048; i += 512) {        // WA: 128x128 hi/lo
        int r = i >> 4, c = (i & 15) << 3;
        *(uint4*)&sWAh[r * WA_PITCH + c] =
            *(const uint4*)(g_WAh + (size_t)(n0A + r) * 1024 + k0A + c);
        *(uint4*)&sWAl[r * WA_PITCH + c] =
            *(const uint4*)(g_WAl + (size_t)(n0A + r) * 1024 + k0A + c);
    }
    for (int i = tid; i < 1024; i += 512) {        // WB: 128x64 hi/lo
        int r = i >> 3, c = (i & 7) << 3;
        *(uint4*)&sWBh[r * WB_PITCH + c] =
            *(const uint4*)(g_WBh + (size_t)(n0B + r) * 1024 + ks0B + c);
        *(uint4*)&sWBl[r * WB_PITCH + c] =
            *(const uint4*)(g_WBl + (size_t)(n0B + r) * 1024 + ks0B + c);
    }
    __syncthreads();

    for (int t = 0; t < T_STEPS; t++) {
        const float* Pt = g_P + (size_t)t * (BATCH * N3);

        // ======== stage A: PA[kcA] slice = h @ WA^T   (64x128 @K=128, weights resident)
        {
            for (int i = tid; i < 1024; i += 512) {
                int r = i >> 4, c = (i & 15) << 3;
                *(uint4*)&sHh[r * WA_PITCH + c] =
                    __ldcg((const uint4*)(g_hbh + (size_t)r * HID + k0A + c));
                *(uint4*)&sHl[r * WA_PITCH + c] =
                    __ldcg((const uint4*)(g_hbl + (size_t)r * HID + k0A + c));
            }
            __syncthreads();

            wmma::fragment<wmma::accumulator, 16, 16, 16, float> acc[2];
            wmma::fill_fragment(acc[0], 0.0f);
            wmma::fill_fragment(acc[1], 0.0f);
#pragma unroll
            for (int kk = 0; kk < 128; kk += 16) {
                wmma::fragment<wmma::matrix_a, 16, 16, 16, __nv_bfloat16, wmma::row_major> fah, fal;
                wmma::fragment<wmma::matrix_b, 16, 16, 16, __nv_bfloat16, wmma::col_major> fbh[2], fbl[2];
                wmma::load_matrix_sync(fah, &sHh[wm * WA_PITCH + kk], WA_PITCH);
                wmma::load_matrix_sync(fal, &sHl[wm * WA_PITCH + kk], WA_PITCH);
#pragma unroll
                for (int j = 0; j < 2; j++) {
                    wmma::load_matrix_sync(fbh[j], &sWAh[(wn + j * 16) * WA_PITCH + kk], WA_PITCH);
                    wmma::load_matrix_sync(fbl[j], &sWAl[(wn + j * 16) * WA_PITCH + kk], WA_PITCH);
                }
#pragma unroll
                for (int j = 0; j < 2; j++) {
                    wmma::mma_sync(acc[j], fah, fbh[j], acc[j]);
                    wmma::mma_sync(acc[j], fah, fbl[j], acc[j]);
                    wmma::mma_sync(acc[j], fal, fbh[j], acc[j]);
                }
            }
#pragma unroll
            for (int j = 0; j < 2; j++)
                wmma::store_matrix_sync(
                    g_PA + (size_t)kcA * (BATCH * 2048) + (size_t)wm * 2048 + n0A + wn + j * 16,
                    acc[j], 2048, wmma::mem_row_major);
            __syncthreads();
        }
        bar_t += NBLK; grid_bar(bar_t);

        // ======== stage B: fused r-reduce + (r*h) @ WB^T   (64x128 @K=64, weights resident)
        {
            for (int idx = tid; idx < 4096; idx += 512) {
                int kl = idx & 63, b = idx >> 6;
                int k = ks0B + kl;
                float s = Pt[b * N3 + 1024 + k];
#pragma unroll
                for (int c = 0; c < 8; c++)
                    s += __ldcg(&g_PA[c * (BATCH * 2048) + b * 2048 + 1024 + k]);
                float r = 1.0f / (1.0f + __expf(-s));
                float rh = r * __ldcg(&g_hb[(b << 10) + k]);
                __nv_bfloat16 hi = __float2bfloat16(rh);
                sHh[b * WA_PITCH + kl] = hi;
                sHl[b * WA_PITCH + kl] = __float2bfloat16(rh - __bfloat162float(hi));
            }
            __syncthreads();

            wmma::fragment<wmma::accumulator, 16, 16, 16, float> acc[2];
            wmma::fill_fragment(acc[0], 0.0f);
            wmma::fill_fragment(acc[1], 0.0f);
#pragma unroll
            for (int kk = 0; kk < 64; kk += 16) {
                wmma::fragment<wmma::matrix_a, 16, 16, 16, __nv_bfloat16, wmma::row_major> fah, fal;
                wmma::fragment<wmma::matrix_b, 16, 16, 16, __nv_bfloat16, wmma::col_major> fbh[2], fbl[2];
                wmma::load_matrix_sync(fah, &sHh[wm * WA_PITCH + kk], WA_PITCH);
                wmma::load_matrix_sync(fal, &sHl[wm * WA_PITCH + kk], WA_PITCH);
#pragma unroll
                for (int j = 0; j < 2; j++) {
                    wmma::load_matrix_sync(fbh[j], &sWBh[(wn + j * 16) * WB_PITCH + kk], WB_PITCH);
                    wmma::load_matrix_sync(fbl[j], &sWBl[(wn + j * 16) * WB_PITCH + kk], WB_PITCH);
                }
#pragma unroll
                for (int j = 0; j < 2; j++) {
                    wmma::mma_sync(acc[j], fah, fbh[j], acc[j]);
                    wmma::mma_sync(acc[j], fah, fbl[j], acc[j]);
                    wmma::mma_sync(acc[j], fal, fbh[j], acc[j]);
                }
            }
#pragma unroll
            for (int j = 0; j < 2; j++)
                wmma::store_matrix_sync(
                    g_PB + (size_t)kcB * (BATCH * 1024) + (size_t)wm * 1024 + n0B + wn + j * 16,
                    acc[j], 1024, wmma::mem_row_major);
            __syncthreads();
        }
        bar_t += NBLK; grid_bar(bar_t);

        // ======== stage C: z reduce + tanh(c) + blend + h update (+ bf16 mirror) + output
        {
            const int o = gtid;                 // exactly one element per thread
            int b = o >> 10, j = o & 1023;
            float sz = Pt[b * N3 + j];
#pragma unroll
            for (int c = 0; c < 8; c++)
                sz += __ldcg(&g_PA[c * (BATCH * 2048) + b * 2048 + j]);
            float z = 1.0f / (1.0f + __expf(-sz));

            float sc = Pt[b * N3 + 2048 + j];
#pragma unroll
            for (int c = 0; c < 16; c++)
                sc += __ldcg(&g_PB[c * (BATCH * 1024) + o]);
            float cv = tanhf(sc);

            float hcur = __ldcg(&g_hb[o]);
            float hn = fmaf(z, cv - hcur, hcur);   // (1-z)*h + z*c
            out[(size_t)t * (BATCH * HID) + o] = hn;
            g_hb[o] = hn;
            __nv_bfloat16 hh = __float2bfloat16(hn);
            g_hbh[o] = hh;
            g_hbl[o] = __float2bfloat16(hn - __bfloat162float(hh));
        }
        bar_t += NBLK; grid_bar(bar_t);
    }
}

// ---------------- launch (4 graph nodes total) ----------------
extern "C" void kernel_launch(void* const* d_in, const int* in_sizes, int n_in,
                              void* d_out, int out_size) {
    const float* x    = (const float*)d_in[0];   // [512, 64, 1024]
    const float* Wfc  = (const float*)d_in[1];   // [2048, 2048]
    const float* Wfc2 = (const float*)d_in[2];   // [1024, 2048]
    // d_in[3] (w_hh), d_in[4] (bias): dead — delta_u never reaches the output
    float* out = (float*)d_out;                  // [512, 64, 1024]

    // One-time dynamic-smem opt-in; never executed during graph capture
    // (first kernel_launch call is the uncaptured correctness run).
    static bool attr_done = false;
    if (!attr_done) {
        cudaFuncSetAttribute(seq_kernel,
                             cudaFuncAttributeMaxDynamicSharedMemorySize, SEQ_SMEM_BYTES);
        attr_done = true;
    }

    init_kernel<<<256, 256>>>();
    convert_kernel<<<(MROWS * DIN + 255) / 256, 256>>>(x, Wfc, Wfc2);
    gemm_p_wmma_kernel<<<(MROWS / 128) * (N3 / 128), 256>>>();
    seq_kernel<<<NBLK, 512, SEQ_SMEM_BYTES>>>(out);
}